// round 15
// baseline (speedup 1.0000x reference)
#include <cuda_runtime.h>
#include <math.h>
#include <stdint.h>

#define D_DIM 1024
#define F_DIM 512
#define N_OUTG 8
#define E_TOT 16
#define T_MAX 1024
#define BM 64
#define BN 64
#define DN_BN 128
#define BK 32
#define RT_TOK 8
#define AS 36           // smem row stride (words): conflict-free frag/ldsm loads

// -------- scratch (no allocation allowed) --------
__device__ int      g_cnt[E_TOT];
__device__ unsigned g_done;
__device__ int      g_list[E_TOT * T_MAX];          // packed (t<<2)|k
__device__ float    g_sel_w[T_MAX * 3];
__device__ unsigned g_H [T_MAX * 3 * F_DIM];        // h = silu(g)*u per pair (tf32 bits)

// ---------------- helpers ----------------
__device__ __forceinline__ unsigned f2tf(float f) {
    unsigned u;
    asm("cvt.rna.tf32.f32 %0, %1;" : "=r"(u) : "f"(f));
    return u;
}
__device__ __forceinline__ uint4 cvt4(float4 v) {
    uint4 r; r.x = f2tf(v.x); r.y = f2tf(v.y); r.z = f2tf(v.z); r.w = f2tf(v.w);
    return r;
}
__device__ __forceinline__ void mma_tf32(float* c, const unsigned* a,
                                         unsigned b0, unsigned b1) {
    asm volatile(
        "mma.sync.aligned.m16n8k8.row.col.f32.tf32.tf32.f32 "
        "{%0,%1,%2,%3}, {%4,%5,%6,%7}, {%8,%9}, {%0,%1,%2,%3};\n"
        : "+f"(c[0]), "+f"(c[1]), "+f"(c[2]), "+f"(c[3])
        : "r"(a[0]), "r"(a[1]), "r"(a[2]), "r"(a[3]), "r"(b0), "r"(b1));
}
__device__ __forceinline__ void ldsm4(unsigned& r0, unsigned& r1,
                                      unsigned& r2, unsigned& r3, uint32_t addr) {
    asm volatile("ldmatrix.sync.aligned.m8n8.x4.shared.b16 {%0,%1,%2,%3}, [%4];"
                 : "=r"(r0), "=r"(r1), "=r"(r2), "=r"(r3) : "r"(addr));
}
__device__ __forceinline__ uint32_t smem_u32(const void* p) {
    uint32_t a;
    asm("{ .reg .u64 t; cvta.to.shared.u64 t, %1; cvt.u32.u64 %0, t; }"
        : "=r"(a) : "l"(p));
    return a;
}

// ======== router v2: 8 tokens/CTA, weights register-resident (L2 traffic /8) =========
// Bit-identical math to the per-token router: same accumulation order, same top-k.
__global__ __launch_bounds__(256)
void router_kernel(const float* __restrict__ x,
                   const float* __restrict__ w_out,
                   const float* __restrict__ w_in,
                   float* __restrict__ out,
                   float* __restrict__ selw_out, int write_selw)
{
    int warp = threadIdx.x >> 5, lane = threadIdx.x & 31;
    __shared__ float s_dots[24];

    // preload this thread's 3 weight-row slices into registers (once per CTA)
    float4 wr[3][8];
    #pragma unroll
    for (int j = 0; j < 3; ++j) {
        int dix = warp * 3 + j;
        const float* w = (dix < N_OUTG) ? (w_out + (size_t)dix * D_DIM)
                                        : (w_in  + (size_t)(dix - N_OUTG) * D_DIM);
        #pragma unroll
        for (int q = 0; q < 8; ++q)
            wr[j][q] = *(const float4*)(w + lane * 4 + q * 128);
    }

    for (int tok = 0; tok < RT_TOK; ++tok) {
        int t = blockIdx.x * RT_TOK + tok;
        const float* xr = x + (size_t)t * D_DIM;

        // zero this token's output row (out is poisoned before each timed run)
        ((float4*)(out + (size_t)t * D_DIM))[threadIdx.x] = make_float4(0.f, 0.f, 0.f, 0.f);

        float4 xv[8];
        #pragma unroll
        for (int q = 0; q < 8; ++q)
            xv[q] = *(const float4*)(xr + lane * 4 + q * 128);

        #pragma unroll
        for (int j = 0; j < 3; ++j) {
            float acc = 0.f;
            #pragma unroll
            for (int q = 0; q < 8; ++q)
                acc += xv[q].x * wr[j][q].x + xv[q].y * wr[j][q].y
                     + xv[q].z * wr[j][q].z + xv[q].w * wr[j][q].w;
            #pragma unroll
            for (int off = 16; off > 0; off >>= 1)
                acc += __shfl_xor_sync(0xffffffffu, acc, off);
            if (lane == 0) s_dots[warp * 3 + j] = acc;
        }
        __syncthreads();

        if (threadIdx.x == 0) {
            float l[N_OUTG];
            #pragma unroll
            for (int i = 0; i < N_OUTG; ++i) l[i] = s_dots[i];
            int a1 = 0;
            #pragma unroll
            for (int i = 1; i < N_OUTG; ++i) if (l[i] > l[a1]) a1 = i;
            int a2 = (a1 == 0) ? 1 : 0;
            #pragma unroll
            for (int i = 0; i < N_OUTG; ++i) if (i != a1 && l[i] > l[a2]) a2 = i;
            float e2 = expf(l[a2] - l[a1]);
            float w0 = 1.f / (1.f + e2);
            float w1 = e2 / (1.f + e2);

            float sA0 = s_dots[8 + a1 * 2], sA1 = s_dots[8 + a1 * 2 + 1];
            int i0 = (sA1 > sA0) ? 1 : 0;
            float sB0 = s_dots[8 + a2 * 2], sB1 = s_dots[8 + a2 * 2 + 1];
            int i2 = (sB1 > sB0) ? 1 : 0;

            int   ids[3] = { a1 * 2 + i0, a1 * 2 + (1 - i0), a2 * 2 + i2 };
            float ws [3] = { w0, w0, w1 };
            #pragma unroll
            for (int k = 0; k < 3; ++k) {
                g_sel_w[t * 3 + k] = ws[k];
                if (write_selw) selw_out[t * 3 + k] = ws[k];
                int e = ids[k];
                int pos = atomicAdd(&g_cnt[e], 1);
                g_list[e * T_MAX + pos] = (t << 2) | k;
            }
        }
        __syncthreads();
    }
}

// ======================= gate+up GEMM (tf32 MMA + ldmatrix, fused SwiGLU) ============
// 64 tokens x 64 f per CTA, 128 threads = 2x2 warps, warp tile 32x32 (R11 layout).
__global__ __launch_bounds__(128)
void gateup_kernel(const float* __restrict__ x,
                   const float* __restrict__ wg,
                   const float* __restrict__ wu)
{
    int e  = blockIdx.y;
    int n  = g_cnt[e];
    int t0 = blockIdx.z * BM;
    if (t0 >= n) return;
    int f0 = blockIdx.x * BN;

    __shared__ unsigned As[BM * AS];
    __shared__ unsigned Gs[BN * AS];
    __shared__ unsigned Us[BN * AS];
    __shared__ int s_pr[BM];

    int tid  = threadIdx.x;
    int warp = tid >> 5, lane = tid & 31;
    int wm = warp >> 1, wn = warp & 1;
    int g  = lane >> 2, t4 = lane & 3;

    if (tid < BM) {
        int rowt = t0 + tid;
        s_pr[tid] = (rowt < n) ? g_list[e * T_MAX + rowt] : -1;
    }
    __syncthreads();

    // global load mapping: thread covers rows {i*16+mi}, k-quad kq
    int mi = tid >> 3, kq = tid & 7;
    const float* wgp = wg + ((size_t)e * F_DIM + f0 + mi) * D_DIM + kq * 4;
    const float* wup = wu + ((size_t)e * F_DIM + f0 + mi) * D_DIM + kq * 4;
    size_t aoff[4];
    #pragma unroll
    for (int i = 0; i < 4; ++i) {
        int pr = s_pr[i * 16 + mi];
        aoff[i] = (size_t)((pr < 0) ? 0 : (pr >> 2)) * D_DIM + kq * 4;
    }

    // ldmatrix per-lane byte offsets
    uint32_t asA = smem_u32(As), asG = smem_u32(Gs), asU = smem_u32(Us);
    uint32_t offA[2], offB[2];
    #pragma unroll
    for (int mf = 0; mf < 2; ++mf)
        offA[mf] = ((wm * 32 + mf * 16 + (lane & 15)) * AS + (lane >> 4) * 4) * 4;
    #pragma unroll
    for (int p = 0; p < 2; ++p)
        offB[p] = ((wn * 32 + p * 16 + ((lane >> 4) << 3) + (lane & 7)) * AS
                   + ((lane >> 3) & 1) * 4) * 4;

    float4 pa[4], pg[4], pu[4];
    #pragma unroll
    for (int i = 0; i < 4; ++i) {
        pa[i] = *(const float4*)(x + aoff[i]);
        pg[i] = *(const float4*)(wgp + (size_t)i * 16 * D_DIM);
        pu[i] = *(const float4*)(wup + (size_t)i * 16 * D_DIM);
    }

    float accG[2][4][4] = {}, accU[2][4][4] = {};

    for (int k0 = 0; k0 < D_DIM; k0 += BK) {
        #pragma unroll
        for (int i = 0; i < 4; ++i) {
            int m = i * 16 + mi;
            *(uint4*)(As + m * AS + kq * 4) = cvt4(pa[i]);
            *(uint4*)(Gs + m * AS + kq * 4) = cvt4(pg[i]);
            *(uint4*)(Us + m * AS + kq * 4) = cvt4(pu[i]);
        }
        __syncthreads();

        int kn = k0 + BK;
        if (kn < D_DIM) {
            #pragma unroll
            for (int i = 0; i < 4; ++i) {
                pa[i] = *(const float4*)(x + aoff[i] + kn);
                pg[i] = *(const float4*)(wgp + kn + (size_t)i * 16 * D_DIM);
                pu[i] = *(const float4*)(wup + kn + (size_t)i * 16 * D_DIM);
            }
        }

        #pragma unroll
        for (int ks = 0; ks < 4; ++ks) {
            unsigned a[2][4], bg[2][4], bu[2][4];
            ldsm4(a[0][0], a[0][1], a[0][2], a[0][3], asA + offA[0] + ks * 32);
            ldsm4(a[1][0], a[1][1], a[1][2], a[1][3], asA + offA[1] + ks * 32);
            ldsm4(bg[0][0], bg[0][1], bg[0][2], bg[0][3], asG + offB[0] + ks * 32);
            ldsm4(bg[1][0], bg[1][1], bg[1][2], bg[1][3], asG + offB[1] + ks * 32);
            ldsm4(bu[0][0], bu[0][1], bu[0][2], bu[0][3], asU + offB[0] + ks * 32);
            ldsm4(bu[1][0], bu[1][1], bu[1][2], bu[1][3], asU + offB[1] + ks * 32);
            #pragma unroll
            for (int p = 0; p < 2; ++p)
                #pragma unroll
                for (int q = 0; q < 2; ++q) {
                    int nf = 2 * p + q;
                    mma_tf32(accG[0][nf], a[0], bg[p][2*q], bg[p][2*q+1]);
                    mma_tf32(accG[1][nf], a[1], bg[p][2*q], bg[p][2*q+1]);
                    mma_tf32(accU[0][nf], a[0], bu[p][2*q], bu[p][2*q+1]);
                    mma_tf32(accU[1][nf], a[1], bu[p][2*q], bu[p][2*q+1]);
                }
        }
        __syncthreads();
    }

    // epilogue: h = silu(g)*u (tf32 bits) scattered to pair rows
    #pragma unroll
    for (int mf = 0; mf < 2; ++mf) {
        #pragma unroll
        for (int h = 0; h < 2; ++h) {
            int m = wm * 32 + mf * 16 + g + h * 8;
            int rowt = t0 + m;
            if (rowt < n) {
                int pr = s_pr[m];
                int prow = (pr >> 2) * 3 + (pr & 3);
                unsigned* Hrow = g_H + (size_t)prow * F_DIM + f0;
                #pragma unroll
                for (int nf = 0; nf < 4; ++nf) {
                    float gv0 = accG[mf][nf][h * 2], gv1 = accG[mf][nf][h * 2 + 1];
                    float uv0 = accU[mf][nf][h * 2], uv1 = accU[mf][nf][h * 2 + 1];
                    float h0 = gv0 / (1.f + expf(-gv0)) * uv0;
                    float h1 = gv1 / (1.f + expf(-gv1)) * uv1;
                    *(uint2*)(Hrow + wn * 32 + nf * 8 + t4 * 2)
                        = make_uint2(f2tf(h0), f2tf(h1));
                }
            }
        }
    }
}

// ========== down GEMM: 64x128 tile, warp tile 32x64 (nf=8), atomics + self-reset =====
__global__ __launch_bounds__(128)
void down_kernel(const float* __restrict__ wd, float* __restrict__ out,
                 unsigned total_ctas)
{
    int e  = blockIdx.y;
    int n  = g_cnt[e];
    int t0 = blockIdx.z * BM;
    int d0 = blockIdx.x * DN_BN;

    __shared__ unsigned Hs[BM * AS];
    __shared__ unsigned Ws[DN_BN * AS];
    __shared__ int s_pr[BM];

    int tid  = threadIdx.x;

    if (t0 < n) {
        int warp = tid >> 5, lane = tid & 31;
        int wm = warp >> 1, wn = warp & 1;
        int g  = lane >> 2, t4 = lane & 3;

        if (tid < BM) {
            int rowt = t0 + tid;
            s_pr[tid] = (rowt < n) ? g_list[e * T_MAX + rowt] : -1;
        }
        __syncthreads();

        int mi = tid >> 3, kq = tid & 7;
        const float* wdp = wd + ((size_t)e * D_DIM + d0 + mi) * F_DIM + kq * 4;
        size_t hoff[4];
        #pragma unroll
        for (int i = 0; i < 4; ++i) {
            int pr = s_pr[i * 16 + mi];
            int prow = (pr < 0) ? 0 : ((pr >> 2) * 3 + (pr & 3));
            hoff[i] = (size_t)prow * F_DIM + kq * 4;
        }

        uint32_t asH = smem_u32(Hs), asW = smem_u32(Ws);
        uint32_t offA[2], offB[4];
        #pragma unroll
        for (int mf = 0; mf < 2; ++mf)
            offA[mf] = ((wm * 32 + mf * 16 + (lane & 15)) * AS + (lane >> 4) * 4) * 4;
        #pragma unroll
        for (int p = 0; p < 4; ++p)
            offB[p] = ((wn * 64 + p * 16 + ((lane >> 4) << 3) + (lane & 7)) * AS
                       + ((lane >> 3) & 1) * 4) * 4;

        uint4 ph[4]; float4 pw[8];
        #pragma unroll
        for (int i = 0; i < 4; ++i)
            ph[i] = *(const uint4*)(g_H + hoff[i]);
        #pragma unroll
        for (int i = 0; i < 8; ++i)
            pw[i] = *(const float4*)(wdp + (size_t)i * 16 * F_DIM);

        float acc[2][8][4] = {};

        for (int k0 = 0; k0 < F_DIM; k0 += BK) {
            #pragma unroll
            for (int i = 0; i < 4; ++i)
                *(uint4*)(Hs + (i * 16 + mi) * AS + kq * 4) = ph[i];
            #pragma unroll
            for (int i = 0; i < 8; ++i)
                *(uint4*)(Ws + (i * 16 + mi) * AS + kq * 4) = cvt4(pw[i]);
            __syncthreads();

            int kn = k0 + BK;
            if (kn < F_DIM) {
                #pragma unroll
                for (int i = 0; i < 4; ++i)
                    ph[i] = *(const uint4*)(g_H + hoff[i] + kn);
                #pragma unroll
                for (int i = 0; i < 8; ++i)
                    pw[i] = *(const float4*)(wdp + kn + (size_t)i * 16 * F_DIM);
            }

            #pragma unroll
            for (int ks = 0; ks < 4; ++ks) {
                unsigned a[2][4], bw[4][4];
                ldsm4(a[0][0], a[0][1], a[0][2], a[0][3], asH + offA[0] + ks * 32);
                ldsm4(a[1][0], a[1][1], a[1][2], a[1][3], asH + offA[1] + ks * 32);
                #pragma unroll
                for (int p = 0; p < 4; ++p)
                    ldsm4(bw[p][0], bw[p][1], bw[p][2], bw[p][3], asW + offB[p] + ks * 32);
                #pragma unroll
                for (int p = 0; p < 4; ++p)
                    #pragma unroll
                    for (int q = 0; q < 2; ++q) {
                        int nf = 2 * p + q;
                        mma_tf32(acc[0][nf], a[0], bw[p][2*q], bw[p][2*q+1]);
                        mma_tf32(acc[1][nf], a[1], bw[p][2*q], bw[p][2*q+1]);
                    }
            }
            __syncthreads();
        }

        // epilogue: weighted atomic accumulate directly into out (REDG, no return)
        #pragma unroll
        for (int mf = 0; mf < 2; ++mf) {
            #pragma unroll
            for (int h = 0; h < 2; ++h) {
                int m = wm * 32 + mf * 16 + g + h * 8;
                int rowt = t0 + m;
                if (rowt < n) {
                    int pr = s_pr[m];
                    int t  = pr >> 2;
                    int prow = t * 3 + (pr & 3);
                    float wsel = g_sel_w[prow];
                    float* Orow = out + (size_t)t * D_DIM + d0;
                    #pragma unroll
                    for (int nf = 0; nf < 8; ++nf) {
                        float y0 = acc[mf][nf][h * 2] * wsel;
                        float y1 = acc[mf][nf][h * 2 + 1] * wsel;
                        atomicAdd(Orow + wn * 64 + nf * 8 + t4 * 2    , y0);
                        atomicAdd(Orow + wn * 64 + nf * 8 + t4 * 2 + 1, y1);
                    }
                }
            }
        }
    }

    // last-CTA counter reset: every CTA (incl. early-exit) tickets AFTER its
    // g_cnt read; the final CTA restores the "counters zero at entry" invariant.
    if (tid == 0) {
        unsigned v = atomicAdd(&g_done, 1);
        if (v == total_ctas - 1) {
            g_done = 0;
            #pragma unroll
            for (int i = 0; i < E_TOT; ++i) g_cnt[i] = 0;
        }
    }
}

// ======================= launch =======================
extern "C" void kernel_launch(void* const* d_in, const int* in_sizes, int n_in,
                              void* d_out, int out_size)
{
    const float* x     = (const float*)d_in[0];
    const float* w_out = (const float*)d_in[1];
    const float* w_in  = (const float*)d_in[2];
    const float* wg    = (const float*)d_in[3];
    const float* wu    = (const float*)d_in[4];
    const float* wd    = (const float*)d_in[5];
    float* out = (float*)d_out;

    int T = in_sizes[0] / D_DIM;
    if (T > T_MAX) T = T_MAX;
    int write_selw = (out_size >= T * D_DIM + 3 * T) ? 1 : 0;

    router_kernel<<<T / RT_TOK, 256>>>(x, w_out, w_in, out,
                                       out + (size_t)T * D_DIM, write_selw);

    int ttiles = (T + BM - 1) / BM;
    dim3 g1(F_DIM / BN, E_TOT, ttiles);
    gateup_kernel<<<g1, 128>>>(x, wg, wu);
    dim3 g2(D_DIM / DN_BN, E_TOT, ttiles);
    unsigned total = g2.x * g2.y * g2.z;
    down_kernel<<<g2, 128>>>(wd, out, total);
}

// round 16
// speedup vs baseline: 1.1293x; 1.1293x over previous
#include <cuda_runtime.h>
#include <math.h>
#include <stdint.h>

#define D_DIM 1024
#define F_DIM 512
#define N_OUTG 8
#define E_TOT 16
#define T_MAX 1024
#define BM 64
#define BN 64
#define DN_BN 128
#define BK 32
#define AS 36           // smem row stride (words): conflict-free frag/ldsm loads

// -------- scratch (no allocation allowed) --------
__device__ int      g_cnt[E_TOT];
__device__ unsigned g_done;
__device__ int      g_list[E_TOT * T_MAX];          // packed (t<<2)|k
__device__ float    g_sel_w[T_MAX * 3];
__device__ unsigned g_H [T_MAX * 3 * F_DIM];        // h = silu(g)*u per pair (tf32 bits)

// ---------------- helpers ----------------
__device__ __forceinline__ unsigned f2tf(float f) {
    unsigned u;
    asm("cvt.rna.tf32.f32 %0, %1;" : "=r"(u) : "f"(f));
    return u;
}
__device__ __forceinline__ uint4 cvt4(float4 v) {
    uint4 r; r.x = f2tf(v.x); r.y = f2tf(v.y); r.z = f2tf(v.z); r.w = f2tf(v.w);
    return r;
}
__device__ __forceinline__ void mma_tf32(float* c, const unsigned* a,
                                         unsigned b0, unsigned b1) {
    asm volatile(
        "mma.sync.aligned.m16n8k8.row.col.f32.tf32.tf32.f32 "
        "{%0,%1,%2,%3}, {%4,%5,%6,%7}, {%8,%9}, {%0,%1,%2,%3};\n"
        : "+f"(c[0]), "+f"(c[1]), "+f"(c[2]), "+f"(c[3])
        : "r"(a[0]), "r"(a[1]), "r"(a[2]), "r"(a[3]), "r"(b0), "r"(b1));
}
__device__ __forceinline__ void ldsm4(unsigned& r0, unsigned& r1,
                                      unsigned& r2, unsigned& r3, uint32_t addr) {
    asm volatile("ldmatrix.sync.aligned.m8n8.x4.shared.b16 {%0,%1,%2,%3}, [%4];"
                 : "=r"(r0), "=r"(r1), "=r"(r2), "=r"(r3) : "r"(addr));
}
__device__ __forceinline__ uint32_t smem_u32(const void* p) {
    uint32_t a;
    asm("{ .reg .u64 t; cvta.to.shared.u64 t, %1; cvt.u32.u64 %0, t; }"
        : "=r"(a) : "l"(p));
    return a;
}

// ======================= router (exact fp32, fused grouping + out zero) ==============
__global__ void router_kernel(const float* __restrict__ x,
                              const float* __restrict__ w_out,
                              const float* __restrict__ w_in,
                              float* __restrict__ out,
                              float* __restrict__ selw_out, int write_selw)
{
    int t = blockIdx.x;
    const float* xr = x + (size_t)t * D_DIM;
    int warp = threadIdx.x >> 5, lane = threadIdx.x & 31;
    __shared__ float s_dots[24];

    // zero this token's output row (out is poisoned before each timed run)
    ((float4*)(out + (size_t)t * D_DIM))[threadIdx.x] = make_float4(0.f, 0.f, 0.f, 0.f);

    #pragma unroll
    for (int j = 0; j < 3; ++j) {
        int dix = warp * 3 + j;
        const float* wr = (dix < N_OUTG) ? (w_out + (size_t)dix * D_DIM)
                                         : (w_in  + (size_t)(dix - N_OUTG) * D_DIM);
        float acc = 0.f;
        for (int k = lane * 4; k < D_DIM; k += 128) {
            float4 a = *(const float4*)(xr + k);
            float4 b = *(const float4*)(wr + k);
            acc += a.x * b.x + a.y * b.y + a.z * b.z + a.w * b.w;
        }
        #pragma unroll
        for (int off = 16; off > 0; off >>= 1)
            acc += __shfl_xor_sync(0xffffffffu, acc, off);
        if (lane == 0) s_dots[dix] = acc;
    }
    __syncthreads();

    if (threadIdx.x == 0) {
        float l[N_OUTG];
        #pragma unroll
        for (int i = 0; i < N_OUTG; ++i) l[i] = s_dots[i];
        int a1 = 0;
        #pragma unroll
        for (int i = 1; i < N_OUTG; ++i) if (l[i] > l[a1]) a1 = i;
        int a2 = (a1 == 0) ? 1 : 0;
        #pragma unroll
        for (int i = 0; i < N_OUTG; ++i) if (i != a1 && l[i] > l[a2]) a2 = i;
        float e2 = expf(l[a2] - l[a1]);
        float w0 = 1.f / (1.f + e2);
        float w1 = e2 / (1.f + e2);

        float sA0 = s_dots[8 + a1 * 2], sA1 = s_dots[8 + a1 * 2 + 1];
        int i0 = (sA1 > sA0) ? 1 : 0;
        float sB0 = s_dots[8 + a2 * 2], sB1 = s_dots[8 + a2 * 2 + 1];
        int i2 = (sB1 > sB0) ? 1 : 0;

        int   ids[3] = { a1 * 2 + i0, a1 * 2 + (1 - i0), a2 * 2 + i2 };
        float ws [3] = { w0, w0, w1 };
        #pragma unroll
        for (int k = 0; k < 3; ++k) {
            g_sel_w[t * 3 + k] = ws[k];
            if (write_selw) selw_out[t * 3 + k] = ws[k];
            int e = ids[k];
            int pos = atomicAdd(&g_cnt[e], 1);
            g_list[e * T_MAX + pos] = (t << 2) | k;
        }
    }
}

// ======================= gate+up GEMM (tf32 MMA + ldmatrix, fused SwiGLU) ============
// 64 tokens x 64 f per CTA, 128 threads = 2x2 warps, warp tile 32x32 (R11 layout).
__global__ __launch_bounds__(128)
void gateup_kernel(const float* __restrict__ x,
                   const float* __restrict__ wg,
                   const float* __restrict__ wu)
{
    int e  = blockIdx.y;
    int n  = g_cnt[e];
    int t0 = blockIdx.z * BM;
    if (t0 >= n) return;
    int f0 = blockIdx.x * BN;

    __shared__ unsigned As[BM * AS];
    __shared__ unsigned Gs[BN * AS];
    __shared__ unsigned Us[BN * AS];
    __shared__ int s_pr[BM];

    int tid  = threadIdx.x;
    int warp = tid >> 5, lane = tid & 31;
    int wm = warp >> 1, wn = warp & 1;
    int g  = lane >> 2, t4 = lane & 3;

    if (tid < BM) {
        int rowt = t0 + tid;
        s_pr[tid] = (rowt < n) ? g_list[e * T_MAX + rowt] : -1;
    }
    __syncthreads();

    // global load mapping: thread covers rows {i*16+mi}, k-quad kq
    int mi = tid >> 3, kq = tid & 7;
    const float* wgp = wg + ((size_t)e * F_DIM + f0 + mi) * D_DIM + kq * 4;
    const float* wup = wu + ((size_t)e * F_DIM + f0 + mi) * D_DIM + kq * 4;
    size_t aoff[4];
    #pragma unroll
    for (int i = 0; i < 4; ++i) {
        int pr = s_pr[i * 16 + mi];
        aoff[i] = (size_t)((pr < 0) ? 0 : (pr >> 2)) * D_DIM + kq * 4;
    }

    // ldmatrix per-lane byte offsets
    uint32_t asA = smem_u32(As), asG = smem_u32(Gs), asU = smem_u32(Us);
    uint32_t offA[2], offB[2];
    #pragma unroll
    for (int mf = 0; mf < 2; ++mf)
        offA[mf] = ((wm * 32 + mf * 16 + (lane & 15)) * AS + (lane >> 4) * 4) * 4;
    #pragma unroll
    for (int p = 0; p < 2; ++p)
        offB[p] = ((wn * 32 + p * 16 + ((lane >> 4) << 3) + (lane & 7)) * AS
                   + ((lane >> 3) & 1) * 4) * 4;

    float4 pa[4], pg[4], pu[4];
    #pragma unroll
    for (int i = 0; i < 4; ++i) {
        pa[i] = *(const float4*)(x + aoff[i]);
        pg[i] = *(const float4*)(wgp + (size_t)i * 16 * D_DIM);
        pu[i] = *(const float4*)(wup + (size_t)i * 16 * D_DIM);
    }

    float accG[2][4][4] = {}, accU[2][4][4] = {};

    for (int k0 = 0; k0 < D_DIM; k0 += BK) {
        #pragma unroll
        for (int i = 0; i < 4; ++i) {
            int m = i * 16 + mi;
            *(uint4*)(As + m * AS + kq * 4) = cvt4(pa[i]);
            *(uint4*)(Gs + m * AS + kq * 4) = cvt4(pg[i]);
            *(uint4*)(Us + m * AS + kq * 4) = cvt4(pu[i]);
        }
        __syncthreads();

        int kn = k0 + BK;
        if (kn < D_DIM) {
            #pragma unroll
            for (int i = 0; i < 4; ++i) {
                pa[i] = *(const float4*)(x + aoff[i] + kn);
                pg[i] = *(const float4*)(wgp + kn + (size_t)i * 16 * D_DIM);
                pu[i] = *(const float4*)(wup + kn + (size_t)i * 16 * D_DIM);
            }
        }

        #pragma unroll
        for (int ks = 0; ks < 4; ++ks) {
            unsigned a[2][4], bg[2][4], bu[2][4];
            ldsm4(a[0][0], a[0][1], a[0][2], a[0][3], asA + offA[0] + ks * 32);
            ldsm4(a[1][0], a[1][1], a[1][2], a[1][3], asA + offA[1] + ks * 32);
            ldsm4(bg[0][0], bg[0][1], bg[0][2], bg[0][3], asG + offB[0] + ks * 32);
            ldsm4(bg[1][0], bg[1][1], bg[1][2], bg[1][3], asG + offB[1] + ks * 32);
            ldsm4(bu[0][0], bu[0][1], bu[0][2], bu[0][3], asU + offB[0] + ks * 32);
            ldsm4(bu[1][0], bu[1][1], bu[1][2], bu[1][3], asU + offB[1] + ks * 32);
            #pragma unroll
            for (int p = 0; p < 2; ++p)
                #pragma unroll
                for (int q = 0; q < 2; ++q) {
                    int nf = 2 * p + q;
                    mma_tf32(accG[0][nf], a[0], bg[p][2*q], bg[p][2*q+1]);
                    mma_tf32(accG[1][nf], a[1], bg[p][2*q], bg[p][2*q+1]);
                    mma_tf32(accU[0][nf], a[0], bu[p][2*q], bu[p][2*q+1]);
                    mma_tf32(accU[1][nf], a[1], bu[p][2*q], bu[p][2*q+1]);
                }
        }
        __syncthreads();
    }

    // epilogue: h = silu(g)*u (tf32 bits) scattered to pair rows
    #pragma unroll
    for (int mf = 0; mf < 2; ++mf) {
        #pragma unroll
        for (int h = 0; h < 2; ++h) {
            int m = wm * 32 + mf * 16 + g + h * 8;
            int rowt = t0 + m;
            if (rowt < n) {
                int pr = s_pr[m];
                int prow = (pr >> 2) * 3 + (pr & 3);
                unsigned* Hrow = g_H + (size_t)prow * F_DIM + f0;
                #pragma unroll
                for (int nf = 0; nf < 4; ++nf) {
                    float gv0 = accG[mf][nf][h * 2], gv1 = accG[mf][nf][h * 2 + 1];
                    float uv0 = accU[mf][nf][h * 2], uv1 = accU[mf][nf][h * 2 + 1];
                    float h0 = gv0 / (1.f + expf(-gv0)) * uv0;
                    float h1 = gv1 / (1.f + expf(-gv1)) * uv1;
                    *(uint2*)(Hrow + wn * 32 + nf * 8 + t4 * 2)
                        = make_uint2(f2tf(h0), f2tf(h1));
                }
            }
        }
    }
}

// ========== down GEMM: 64x128 tile, warp tile 32x64 (nf=8), atomics + self-reset =====
__global__ __launch_bounds__(128)
void down_kernel(const float* __restrict__ wd, float* __restrict__ out,
                 unsigned total_ctas)
{
    int e  = blockIdx.y;
    int n  = g_cnt[e];
    int t0 = blockIdx.z * BM;
    int d0 = blockIdx.x * DN_BN;

    __shared__ unsigned Hs[BM * AS];
    __shared__ unsigned Ws[DN_BN * AS];
    __shared__ int s_pr[BM];

    int tid  = threadIdx.x;

    if (t0 < n) {
        int warp = tid >> 5, lane = tid & 31;
        int wm = warp >> 1, wn = warp & 1;
        int g  = lane >> 2, t4 = lane & 3;

        if (tid < BM) {
            int rowt = t0 + tid;
            s_pr[tid] = (rowt < n) ? g_list[e * T_MAX + rowt] : -1;
        }
        __syncthreads();

        int mi = tid >> 3, kq = tid & 7;
        const float* wdp = wd + ((size_t)e * D_DIM + d0 + mi) * F_DIM + kq * 4;
        size_t hoff[4];
        #pragma unroll
        for (int i = 0; i < 4; ++i) {
            int pr = s_pr[i * 16 + mi];
            int prow = (pr < 0) ? 0 : ((pr >> 2) * 3 + (pr & 3));
            hoff[i] = (size_t)prow * F_DIM + kq * 4;
        }

        uint32_t asH = smem_u32(Hs), asW = smem_u32(Ws);
        uint32_t offA[2], offB[4];
        #pragma unroll
        for (int mf = 0; mf < 2; ++mf)
            offA[mf] = ((wm * 32 + mf * 16 + (lane & 15)) * AS + (lane >> 4) * 4) * 4;
        #pragma unroll
        for (int p = 0; p < 4; ++p)
            offB[p] = ((wn * 64 + p * 16 + ((lane >> 4) << 3) + (lane & 7)) * AS
                       + ((lane >> 3) & 1) * 4) * 4;

        uint4 ph[4]; float4 pw[8];
        #pragma unroll
        for (int i = 0; i < 4; ++i)
            ph[i] = *(const uint4*)(g_H + hoff[i]);
        #pragma unroll
        for (int i = 0; i < 8; ++i)
            pw[i] = *(const float4*)(wdp + (size_t)i * 16 * F_DIM);

        float acc[2][8][4] = {};

        for (int k0 = 0; k0 < F_DIM; k0 += BK) {
            #pragma unroll
            for (int i = 0; i < 4; ++i)
                *(uint4*)(Hs + (i * 16 + mi) * AS + kq * 4) = ph[i];
            #pragma unroll
            for (int i = 0; i < 8; ++i)
                *(uint4*)(Ws + (i * 16 + mi) * AS + kq * 4) = cvt4(pw[i]);
            __syncthreads();

            int kn = k0 + BK;
            if (kn < F_DIM) {
                #pragma unroll
                for (int i = 0; i < 4; ++i)
                    ph[i] = *(const uint4*)(g_H + hoff[i] + kn);
                #pragma unroll
                for (int i = 0; i < 8; ++i)
                    pw[i] = *(const float4*)(wdp + kn + (size_t)i * 16 * F_DIM);
            }

            #pragma unroll
            for (int ks = 0; ks < 4; ++ks) {
                unsigned a[2][4], bw[4][4];
                ldsm4(a[0][0], a[0][1], a[0][2], a[0][3], asH + offA[0] + ks * 32);
                ldsm4(a[1][0], a[1][1], a[1][2], a[1][3], asH + offA[1] + ks * 32);
                #pragma unroll
                for (int p = 0; p < 4; ++p)
                    ldsm4(bw[p][0], bw[p][1], bw[p][2], bw[p][3], asW + offB[p] + ks * 32);
                #pragma unroll
                for (int p = 0; p < 4; ++p)
                    #pragma unroll
                    for (int q = 0; q < 2; ++q) {
                        int nf = 2 * p + q;
                        mma_tf32(acc[0][nf], a[0], bw[p][2*q], bw[p][2*q+1]);
                        mma_tf32(acc[1][nf], a[1], bw[p][2*q], bw[p][2*q+1]);
                    }
            }
            __syncthreads();
        }

        // epilogue: weighted atomic accumulate directly into out (REDG, no return)
        #pragma unroll
        for (int mf = 0; mf < 2; ++mf) {
            #pragma unroll
            for (int h = 0; h < 2; ++h) {
                int m = wm * 32 + mf * 16 + g + h * 8;
                int rowt = t0 + m;
                if (rowt < n) {
                    int pr = s_pr[m];
                    int t  = pr >> 2;
                    int prow = t * 3 + (pr & 3);
                    float wsel = g_sel_w[prow];
                    float* Orow = out + (size_t)t * D_DIM + d0;
                    #pragma unroll
                    for (int nf = 0; nf < 8; ++nf) {
                        float y0 = acc[mf][nf][h * 2] * wsel;
                        float y1 = acc[mf][nf][h * 2 + 1] * wsel;
                        atomicAdd(Orow + wn * 64 + nf * 8 + t4 * 2    , y0);
                        atomicAdd(Orow + wn * 64 + nf * 8 + t4 * 2 + 1, y1);
                    }
                }
            }
        }
    }

    // last-CTA counter reset: every CTA (incl. early-exit) tickets AFTER its
    // g_cnt read; the final CTA restores the "counters zero at entry" invariant.
    if (tid == 0) {
        unsigned v = atomicAdd(&g_done, 1);
        if (v == total_ctas - 1) {
            g_done = 0;
            #pragma unroll
            for (int i = 0; i < E_TOT; ++i) g_cnt[i] = 0;
        }
    }
}

// ======================= launch =======================
extern "C" void kernel_launch(void* const* d_in, const int* in_sizes, int n_in,
                              void* d_out, int out_size)
{
    const float* x     = (const float*)d_in[0];
    const float* w_out = (const float*)d_in[1];
    const float* w_in  = (const float*)d_in[2];
    const float* wg    = (const float*)d_in[3];
    const float* wu    = (const float*)d_in[4];
    const float* wd    = (const float*)d_in[5];
    float* out = (float*)d_out;

    int T = in_sizes[0] / D_DIM;
    if (T > T_MAX) T = T_MAX;
    int write_selw = (out_size >= T * D_DIM + 3 * T) ? 1 : 0;

    router_kernel<<<T, 256>>>(x, w_out, w_in, out,
                              out + (size_t)T * D_DIM, write_selw);

    int ttiles = (T + BM - 1) / BM;
    dim3 g1(F_DIM / BN, E_TOT, ttiles);
    gateup_kernel<<<g1, 128>>>(x, wg, wu);
    dim3 g2(D_DIM / DN_BN, E_TOT, ttiles);
    unsigned total = g2.x * g2.y * g2.z;
    down_kernel<<<g2, 128>>>(wd, out, total);
}

// round 17
// speedup vs baseline: 1.1395x; 1.0090x over previous
#include <cuda_runtime.h>
#include <math.h>
#include <stdint.h>

#define D_DIM 1024
#define F_DIM 512
#define N_OUTG 8
#define E_TOT 16
#define T_MAX 1024
#define BM 64
#define BN 64
#define DN_BN 128
#define BK 32
#define AS 36           // smem row stride (words): conflict-free frag/ldsm loads

// -------- scratch (no allocation allowed) --------
__device__ int      g_cnt[E_TOT];
__device__ unsigned g_done;
__device__ int      g_list[E_TOT * T_MAX];          // packed (t<<2)|k
__device__ float    g_sel_w[T_MAX * 3];
__device__ unsigned g_H [T_MAX * 3 * F_DIM];        // h = silu(g)*u per pair (tf32 bits)

// ---------------- helpers ----------------
__device__ __forceinline__ unsigned f2tf(float f) {
    unsigned u;
    asm("cvt.rna.tf32.f32 %0, %1;" : "=r"(u) : "f"(f));
    return u;
}
__device__ __forceinline__ uint4 cvt4(float4 v) {
    uint4 r; r.x = f2tf(v.x); r.y = f2tf(v.y); r.z = f2tf(v.z); r.w = f2tf(v.w);
    return r;
}
__device__ __forceinline__ void mma_tf32(float* c, const unsigned* a,
                                         unsigned b0, unsigned b1) {
    asm volatile(
        "mma.sync.aligned.m16n8k8.row.col.f32.tf32.tf32.f32 "
        "{%0,%1,%2,%3}, {%4,%5,%6,%7}, {%8,%9}, {%0,%1,%2,%3};\n"
        : "+f"(c[0]), "+f"(c[1]), "+f"(c[2]), "+f"(c[3])
        : "r"(a[0]), "r"(a[1]), "r"(a[2]), "r"(a[3]), "r"(b0), "r"(b1));
}
__device__ __forceinline__ void ldsm4(unsigned& r0, unsigned& r1,
                                      unsigned& r2, unsigned& r3, uint32_t addr) {
    asm volatile("ldmatrix.sync.aligned.m8n8.x4.shared.b16 {%0,%1,%2,%3}, [%4];"
                 : "=r"(r0), "=r"(r1), "=r"(r2), "=r"(r3) : "r"(addr));
}
__device__ __forceinline__ uint32_t smem_u32(const void* p) {
    uint32_t a;
    asm("{ .reg .u64 t; cvta.to.shared.u64 t, %1; cvt.u32.u64 %0, t; }"
        : "=r"(a) : "l"(p));
    return a;
}

// ========== router (exact fp32, register-batched loads, fused grouping + zero) =======
// Same accumulation order as before (q ascending, same lane partials) -> bit-identical.
__global__ __launch_bounds__(256)
void router_kernel(const float* __restrict__ x,
                   const float* __restrict__ w_out,
                   const float* __restrict__ w_in,
                   float* __restrict__ out,
                   float* __restrict__ selw_out, int write_selw)
{
    int t = blockIdx.x;
    const float* xr = x + (size_t)t * D_DIM;
    int warp = threadIdx.x >> 5, lane = threadIdx.x & 31;
    __shared__ float s_dots[24];

    // zero this token's output row (out is poisoned before each timed run)
    ((float4*)(out + (size_t)t * D_DIM))[threadIdx.x] = make_float4(0.f, 0.f, 0.f, 0.f);

    // batch-load x slice once (reused for all 3 dots of this warp)
    float4 xv[8];
    #pragma unroll
    for (int q = 0; q < 8; ++q)
        xv[q] = *(const float4*)(xr + lane * 4 + q * 128);

    #pragma unroll
    for (int j = 0; j < 3; ++j) {
        int dix = warp * 3 + j;
        const float* wr = (dix < N_OUTG) ? (w_out + (size_t)dix * D_DIM)
                                         : (w_in  + (size_t)(dix - N_OUTG) * D_DIM);
        // batch-load weight slice (MLP=8 outstanding LDG.128)
        float4 wv[8];
        #pragma unroll
        for (int q = 0; q < 8; ++q)
            wv[q] = *(const float4*)(wr + lane * 4 + q * 128);

        float acc = 0.f;
        #pragma unroll
        for (int q = 0; q < 8; ++q)
            acc += xv[q].x * wv[q].x + xv[q].y * wv[q].y
                 + xv[q].z * wv[q].z + xv[q].w * wv[q].w;
        #pragma unroll
        for (int off = 16; off > 0; off >>= 1)
            acc += __shfl_xor_sync(0xffffffffu, acc, off);
        if (lane == 0) s_dots[dix] = acc;
    }
    __syncthreads();

    if (threadIdx.x == 0) {
        float l[N_OUTG];
        #pragma unroll
        for (int i = 0; i < N_OUTG; ++i) l[i] = s_dots[i];
        int a1 = 0;
        #pragma unroll
        for (int i = 1; i < N_OUTG; ++i) if (l[i] > l[a1]) a1 = i;
        int a2 = (a1 == 0) ? 1 : 0;
        #pragma unroll
        for (int i = 0; i < N_OUTG; ++i) if (i != a1 && l[i] > l[a2]) a2 = i;
        float e2 = expf(l[a2] - l[a1]);
        float w0 = 1.f / (1.f + e2);
        float w1 = e2 / (1.f + e2);

        float sA0 = s_dots[8 + a1 * 2], sA1 = s_dots[8 + a1 * 2 + 1];
        int i0 = (sA1 > sA0) ? 1 : 0;
        float sB0 = s_dots[8 + a2 * 2], sB1 = s_dots[8 + a2 * 2 + 1];
        int i2 = (sB1 > sB0) ? 1 : 0;

        int   ids[3] = { a1 * 2 + i0, a1 * 2 + (1 - i0), a2 * 2 + i2 };
        float ws [3] = { w0, w0, w1 };
        #pragma unroll
        for (int k = 0; k < 3; ++k) {
            g_sel_w[t * 3 + k] = ws[k];
            if (write_selw) selw_out[t * 3 + k] = ws[k];
            int e = ids[k];
            int pos = atomicAdd(&g_cnt[e], 1);
            g_list[e * T_MAX + pos] = (t << 2) | k;
        }
    }
}

// ======================= gate+up GEMM (tf32 MMA + ldmatrix, fused SwiGLU) ============
// 64 tokens x 64 f per CTA, 128 threads = 2x2 warps, warp tile 32x32 (R11 layout).
__global__ __launch_bounds__(128)
void gateup_kernel(const float* __restrict__ x,
                   const float* __restrict__ wg,
                   const float* __restrict__ wu)
{
    int e  = blockIdx.y;
    int n  = g_cnt[e];
    int t0 = blockIdx.z * BM;
    if (t0 >= n) return;
    int f0 = blockIdx.x * BN;

    __shared__ unsigned As[BM * AS];
    __shared__ unsigned Gs[BN * AS];
    __shared__ unsigned Us[BN * AS];
    __shared__ int s_pr[BM];

    int tid  = threadIdx.x;
    int warp = tid >> 5, lane = tid & 31;
    int wm = warp >> 1, wn = warp & 1;
    int g  = lane >> 2, t4 = lane & 3;

    if (tid < BM) {
        int rowt = t0 + tid;
        s_pr[tid] = (rowt < n) ? g_list[e * T_MAX + rowt] : -1;
    }
    __syncthreads();

    // global load mapping: thread covers rows {i*16+mi}, k-quad kq
    int mi = tid >> 3, kq = tid & 7;
    const float* wgp = wg + ((size_t)e * F_DIM + f0 + mi) * D_DIM + kq * 4;
    const float* wup = wu + ((size_t)e * F_DIM + f0 + mi) * D_DIM + kq * 4;
    size_t aoff[4];
    #pragma unroll
    for (int i = 0; i < 4; ++i) {
        int pr = s_pr[i * 16 + mi];
        aoff[i] = (size_t)((pr < 0) ? 0 : (pr >> 2)) * D_DIM + kq * 4;
    }

    // ldmatrix per-lane byte offsets
    uint32_t asA = smem_u32(As), asG = smem_u32(Gs), asU = smem_u32(Us);
    uint32_t offA[2], offB[2];
    #pragma unroll
    for (int mf = 0; mf < 2; ++mf)
        offA[mf] = ((wm * 32 + mf * 16 + (lane & 15)) * AS + (lane >> 4) * 4) * 4;
    #pragma unroll
    for (int p = 0; p < 2; ++p)
        offB[p] = ((wn * 32 + p * 16 + ((lane >> 4) << 3) + (lane & 7)) * AS
                   + ((lane >> 3) & 1) * 4) * 4;

    float4 pa[4], pg[4], pu[4];
    #pragma unroll
    for (int i = 0; i < 4; ++i) {
        pa[i] = *(const float4*)(x + aoff[i]);
        pg[i] = *(const float4*)(wgp + (size_t)i * 16 * D_DIM);
        pu[i] = *(const float4*)(wup + (size_t)i * 16 * D_DIM);
    }

    float accG[2][4][4] = {}, accU[2][4][4] = {};

    for (int k0 = 0; k0 < D_DIM; k0 += BK) {
        #pragma unroll
        for (int i = 0; i < 4; ++i) {
            int m = i * 16 + mi;
            *(uint4*)(As + m * AS + kq * 4) = cvt4(pa[i]);
            *(uint4*)(Gs + m * AS + kq * 4) = cvt4(pg[i]);
            *(uint4*)(Us + m * AS + kq * 4) = cvt4(pu[i]);
        }
        __syncthreads();

        int kn = k0 + BK;
        if (kn < D_DIM) {
            #pragma unroll
            for (int i = 0; i < 4; ++i) {
                pa[i] = *(const float4*)(x + aoff[i] + kn);
                pg[i] = *(const float4*)(wgp + kn + (size_t)i * 16 * D_DIM);
                pu[i] = *(const float4*)(wup + kn + (size_t)i * 16 * D_DIM);
            }
        }

        #pragma unroll
        for (int ks = 0; ks < 4; ++ks) {
            unsigned a[2][4], bg[2][4], bu[2][4];
            ldsm4(a[0][0], a[0][1], a[0][2], a[0][3], asA + offA[0] + ks * 32);
            ldsm4(a[1][0], a[1][1], a[1][2], a[1][3], asA + offA[1] + ks * 32);
            ldsm4(bg[0][0], bg[0][1], bg[0][2], bg[0][3], asG + offB[0] + ks * 32);
            ldsm4(bg[1][0], bg[1][1], bg[1][2], bg[1][3], asG + offB[1] + ks * 32);
            ldsm4(bu[0][0], bu[0][1], bu[0][2], bu[0][3], asU + offB[0] + ks * 32);
            ldsm4(bu[1][0], bu[1][1], bu[1][2], bu[1][3], asU + offB[1] + ks * 32);
            #pragma unroll
            for (int p = 0; p < 2; ++p)
                #pragma unroll
                for (int q = 0; q < 2; ++q) {
                    int nf = 2 * p + q;
                    mma_tf32(accG[0][nf], a[0], bg[p][2*q], bg[p][2*q+1]);
                    mma_tf32(accG[1][nf], a[1], bg[p][2*q], bg[p][2*q+1]);
                    mma_tf32(accU[0][nf], a[0], bu[p][2*q], bu[p][2*q+1]);
                    mma_tf32(accU[1][nf], a[1], bu[p][2*q], bu[p][2*q+1]);
                }
        }
        __syncthreads();
    }

    // epilogue: h = silu(g)*u (tf32 bits) scattered to pair rows
    #pragma unroll
    for (int mf = 0; mf < 2; ++mf) {
        #pragma unroll
        for (int h = 0; h < 2; ++h) {
            int m = wm * 32 + mf * 16 + g + h * 8;
            int rowt = t0 + m;
            if (rowt < n) {
                int pr = s_pr[m];
                int prow = (pr >> 2) * 3 + (pr & 3);
                unsigned* Hrow = g_H + (size_t)prow * F_DIM + f0;
                #pragma unroll
                for (int nf = 0; nf < 4; ++nf) {
                    float gv0 = accG[mf][nf][h * 2], gv1 = accG[mf][nf][h * 2 + 1];
                    float uv0 = accU[mf][nf][h * 2], uv1 = accU[mf][nf][h * 2 + 1];
                    float h0 = gv0 / (1.f + expf(-gv0)) * uv0;
                    float h1 = gv1 / (1.f + expf(-gv1)) * uv1;
                    *(uint2*)(Hrow + wn * 32 + nf * 8 + t4 * 2)
                        = make_uint2(f2tf(h0), f2tf(h1));
                }
            }
        }
    }
}

// ========== down GEMM: 64x128 tile, warp tile 32x64 (nf=8), atomics + self-reset =====
__global__ __launch_bounds__(128)
void down_kernel(const float* __restrict__ wd, float* __restrict__ out,
                 unsigned total_ctas)
{
    int e  = blockIdx.y;
    int n  = g_cnt[e];
    int t0 = blockIdx.z * BM;
    int d0 = blockIdx.x * DN_BN;

    __shared__ unsigned Hs[BM * AS];
    __shared__ unsigned Ws[DN_BN * AS];
    __shared__ int s_pr[BM];

    int tid  = threadIdx.x;

    if (t0 < n) {
        int warp = tid >> 5, lane = tid & 31;
        int wm = warp >> 1, wn = warp & 1;
        int g  = lane >> 2, t4 = lane & 3;

        if (tid < BM) {
            int rowt = t0 + tid;
            s_pr[tid] = (rowt < n) ? g_list[e * T_MAX + rowt] : -1;
        }
        __syncthreads();

        int mi = tid >> 3, kq = tid & 7;
        const float* wdp = wd + ((size_t)e * D_DIM + d0 + mi) * F_DIM + kq * 4;
        size_t hoff[4];
        #pragma unroll
        for (int i = 0; i < 4; ++i) {
            int pr = s_pr[i * 16 + mi];
            int prow = (pr < 0) ? 0 : ((pr >> 2) * 3 + (pr & 3));
            hoff[i] = (size_t)prow * F_DIM + kq * 4;
        }

        uint32_t asH = smem_u32(Hs), asW = smem_u32(Ws);
        uint32_t offA[2], offB[4];
        #pragma unroll
        for (int mf = 0; mf < 2; ++mf)
            offA[mf] = ((wm * 32 + mf * 16 + (lane & 15)) * AS + (lane >> 4) * 4) * 4;
        #pragma unroll
        for (int p = 0; p < 4; ++p)
            offB[p] = ((wn * 64 + p * 16 + ((lane >> 4) << 3) + (lane & 7)) * AS
                       + ((lane >> 3) & 1) * 4) * 4;

        uint4 ph[4]; float4 pw[8];
        #pragma unroll
        for (int i = 0; i < 4; ++i)
            ph[i] = *(const uint4*)(g_H + hoff[i]);
        #pragma unroll
        for (int i = 0; i < 8; ++i)
            pw[i] = *(const float4*)(wdp + (size_t)i * 16 * F_DIM);

        float acc[2][8][4] = {};

        for (int k0 = 0; k0 < F_DIM; k0 += BK) {
            #pragma unroll
            for (int i = 0; i < 4; ++i)
                *(uint4*)(Hs + (i * 16 + mi) * AS + kq * 4) = ph[i];
            #pragma unroll
            for (int i = 0; i < 8; ++i)
                *(uint4*)(Ws + (i * 16 + mi) * AS + kq * 4) = cvt4(pw[i]);
            __syncthreads();

            int kn = k0 + BK;
            if (kn < F_DIM) {
                #pragma unroll
                for (int i = 0; i < 4; ++i)
                    ph[i] = *(const uint4*)(g_H + hoff[i] + kn);
                #pragma unroll
                for (int i = 0; i < 8; ++i)
                    pw[i] = *(const float4*)(wdp + kn + (size_t)i * 16 * F_DIM);
            }

            #pragma unroll
            for (int ks = 0; ks < 4; ++ks) {
                unsigned a[2][4], bw[4][4];
                ldsm4(a[0][0], a[0][1], a[0][2], a[0][3], asH + offA[0] + ks * 32);
                ldsm4(a[1][0], a[1][1], a[1][2], a[1][3], asH + offA[1] + ks * 32);
                #pragma unroll
                for (int p = 0; p < 4; ++p)
                    ldsm4(bw[p][0], bw[p][1], bw[p][2], bw[p][3], asW + offB[p] + ks * 32);
                #pragma unroll
                for (int p = 0; p < 4; ++p)
                    #pragma unroll
                    for (int q = 0; q < 2; ++q) {
                        int nf = 2 * p + q;
                        mma_tf32(acc[0][nf], a[0], bw[p][2*q], bw[p][2*q+1]);
                        mma_tf32(acc[1][nf], a[1], bw[p][2*q], bw[p][2*q+1]);
                    }
            }
            __syncthreads();
        }

        // epilogue: weighted atomic accumulate directly into out (REDG, no return)
        #pragma unroll
        for (int mf = 0; mf < 2; ++mf) {
            #pragma unroll
            for (int h = 0; h < 2; ++h) {
                int m = wm * 32 + mf * 16 + g + h * 8;
                int rowt = t0 + m;
                if (rowt < n) {
                    int pr = s_pr[m];
                    int t  = pr >> 2;
                    int prow = t * 3 + (pr & 3);
                    float wsel = g_sel_w[prow];
                    float* Orow = out + (size_t)t * D_DIM + d0;
                    #pragma unroll
                    for (int nf = 0; nf < 8; ++nf) {
                        float y0 = acc[mf][nf][h * 2] * wsel;
                        float y1 = acc[mf][nf][h * 2 + 1] * wsel;
                        atomicAdd(Orow + wn * 64 + nf * 8 + t4 * 2    , y0);
                        atomicAdd(Orow + wn * 64 + nf * 8 + t4 * 2 + 1, y1);
                    }
                }
            }
        }
    }

    // last-CTA counter reset: every CTA (incl. early-exit) tickets AFTER its
    // g_cnt read; the final CTA restores the "counters zero at entry" invariant.
    if (tid == 0) {
        unsigned v = atomicAdd(&g_done, 1);
        if (v == total_ctas - 1) {
            g_done = 0;
            #pragma unroll
            for (int i = 0; i < E_TOT; ++i) g_cnt[i] = 0;
        }
    }
}

// ======================= launch =======================
extern "C" void kernel_launch(void* const* d_in, const int* in_sizes, int n_in,
                              void* d_out, int out_size)
{
    const float* x     = (const float*)d_in[0];
    const float* w_out = (const float*)d_in[1];
    const float* w_in  = (const float*)d_in[2];
    const float* wg    = (const float*)d_in[3];
    const float* wu    = (const float*)d_in[4];
    const float* wd    = (const float*)d_in[5];
    float* out = (float*)d_out;

    int T = in_sizes[0] / D_DIM;
    if (T > T_MAX) T = T_MAX;
    int write_selw = (out_size >= T * D_DIM + 3 * T) ? 1 : 0;

    router_kernel<<<T, 256>>>(x, w_out, w_in, out,
                              out + (size_t)T * D_DIM, write_selw);

    int ttiles = (T + BM - 1) / BM;
    dim3 g1(F_DIM / BN, E_TOT, ttiles);
    gateup_kernel<<<g1, 128>>>(x, wg, wu);
    dim3 g2(D_DIM / DN_BN, E_TOT, ttiles);
    unsigned total = g2.x * g2.y * g2.z;
    down_kernel<<<g2, 128>>>(wd, out, total);
}